// round 7
// baseline (speedup 1.0000x reference)
#include <cuda_runtime.h>
#include <math.h>

#define L_DENSE   1024
#define LT        64
#define ROWS_BLK  8
#define XS_STR    1028    // floats per row in smem; 1028 % 32 == 4 -> row step = 4 banks
#define OUT_STR   260     // floats per row for partials [k*4 + h]; 260 % 32 == 4

// Precomputed band: l0[k] = start column of 64-wide window; Wt[k][h*16+j] = W at offset 4j+h
__device__ int   g_l0[LT];
__device__ float g_Wt[LT * LT];

__global__ void precompute_kernel(const float* __restrict__ weight) {
    int k = threadIdx.x;
    if (k >= LT) return;
    float wk = weight[k];
    // center the 64-wide band on wk (t = l+1), clamp to valid range
    int l0 = (int)floorf(wk + 0.5f) - 33;
    l0 = max(0, min(L_DENSE - LT, l0));
    g_l0[k] = l0;
    #pragma unroll 4
    for (int h = 0; h < 4; ++h) {
        for (int j = 0; j < 16; ++j) {
            int jj = 4 * j + h;
            float d = (float)(l0 + jj + 1) - wk;
            g_Wt[k * LT + h * 16 + j] = expf(-d * d * 0.01f);
        }
    }
}

__global__ void __launch_bounds__(256) sampling_kernel(
    const float* __restrict__ x, float* __restrict__ out, int rows)
{
    __shared__ __align__(16) float xs[ROWS_BLK * XS_STR];     // 32896 B
    __shared__ __align__(16) float outs4[ROWS_BLK * OUT_STR]; //  8320 B

    const int tid = threadIdx.x;
    const int r0  = blockIdx.x * ROWS_BLK;

    // ---- Stage 8 rows of x into smem: coalesced float4 loads, conflict-free STS.128 ----
    {
        const float4* xg = reinterpret_cast<const float4*>(x) + (size_t)r0 * (L_DENSE / 4);
        #pragma unroll
        for (int it = 0; it < (ROWS_BLK * L_DENSE / 4) / 256; ++it) {
            int i   = tid + it * 256;            // 0..2047
            int row = i >> 8;                    // 256 float4 per row
            int c4  = i & 255;
            float4 v = make_float4(0.f, 0.f, 0.f, 0.f);
            if (r0 + row < rows) v = xg[row * (L_DENSE / 4) + c4];
            *reinterpret_cast<float4*>(&xs[row * XS_STR + c4 * 4]) = v;
        }
    }
    __syncthreads();

    // ---- Banded dot products ----
    // lane = rowl (0..7) + 8*h (0..3). Lane handles x indices l0k + 4j + h, j=0..15.
    // smem word residue = 4*rowl + h + const  -> 32 distinct banks -> conflict-free.
    {
        const int warp = tid >> 5;
        const int lane = tid & 31;
        const int h    = lane >> 3;
        const int rowl = lane & 7;
        const float* xr = xs + rowl * XS_STR;

        // Hoist window bases off the dependent address path
        int l0r[8];
        #pragma unroll
        for (int it = 0; it < 8; ++it) l0r[it] = g_l0[(warp << 3) | it];

        #pragma unroll
        for (int it = 0; it < 8; ++it) {
            const int k   = (warp << 3) | it;
            const float4* wt = reinterpret_cast<const float4*>(g_Wt + (k << 6) + (h << 4));
            const float* xb = xr + l0r[it] + h;

            float4 w0 = wt[0], w1 = wt[1], w2 = wt[2], w3 = wt[3];
            float a0 = 0.f, a1 = 0.f;   // two chains for ILP
            a0 = fmaf(xb[ 0], w0.x, a0);  a1 = fmaf(xb[ 4], w0.y, a1);
            a0 = fmaf(xb[ 8], w0.z, a0);  a1 = fmaf(xb[12], w0.w, a1);
            a0 = fmaf(xb[16], w1.x, a0);  a1 = fmaf(xb[20], w1.y, a1);
            a0 = fmaf(xb[24], w1.z, a0);  a1 = fmaf(xb[28], w1.w, a1);
            a0 = fmaf(xb[32], w2.x, a0);  a1 = fmaf(xb[36], w2.y, a1);
            a0 = fmaf(xb[40], w2.z, a0);  a1 = fmaf(xb[44], w2.w, a1);
            a0 = fmaf(xb[48], w3.x, a0);  a1 = fmaf(xb[52], w3.y, a1);
            a0 = fmaf(xb[56], w3.z, a0);  a1 = fmaf(xb[60], w3.w, a1);

            // partial per (row, k, h); residue 4*rowl + h -> conflict-free STS
            outs4[rowl * OUT_STR + (k << 2) + h] = a0 + a1;
        }
    }
    __syncthreads();

    // ---- Reduce the 4 phase-partials and write out coalesced ----
    #pragma unroll
    for (int it = 0; it < (ROWS_BLK * LT) / 256; ++it) {
        int i   = tid + it * 256;    // 0..511
        int row = i >> 6;
        int k   = i & 63;
        float4 p = *reinterpret_cast<const float4*>(&outs4[row * OUT_STR + (k << 2)]);
        if (r0 + row < rows)
            out[(size_t)(r0 + row) * LT + k] = (p.x + p.y) + (p.z + p.w);
    }
}

extern "C" void kernel_launch(void* const* d_in, const int* in_sizes, int n_in,
                              void* d_out, int out_size) {
    const float* x      = (const float*)d_in[0];
    const float* weight = (const float*)d_in[1];
    float* out          = (float*)d_out;

    const int rows = in_sizes[0] / L_DENSE;           // B * NUM_ADC_P = 131072

    precompute_kernel<<<1, 64>>>(weight);
    const int grid = (rows + ROWS_BLK - 1) / ROWS_BLK; // 16384
    sampling_kernel<<<grid, 256>>>(x, out, rows);
}

// round 10
// speedup vs baseline: 1.2854x; 1.2854x over previous
#include <cuda_runtime.h>
#include <cuda_fp16.h>
#include <cstdint>
#include <math.h>

#define L_DENSE 1024
#define LT      64
#define NSTEPS  64        // K / 16
#define MTILE   128       // rows per CTA (4 warps x 32)
#define THREADS 128

// W fragments for mma.m16n8k16.row.col, fragment-linear:
// g_Bfrag[ks*256 + nt*32 + lane] = { half2(W[n][k0],W[n][k0+1]), half2(W[n][k0+8],W[n][k0+9]) }
// with n = nt*8 + lane/4, k0 = ks*16 + (lane%4)*2, W[n][k] = exp(-((k+1)-w_n)^2/100)
__device__ uint2 g_Bfrag[NSTEPS * 8 * 32];

static __device__ __forceinline__ uint32_t f2_h2(float lo, float hi) {
    uint32_t u;
    asm("cvt.rn.f16x2.f32 %0, %1, %2;" : "=r"(u) : "f"(hi), "f"(lo));
    return u;
}

__global__ void precompute_frag(const float* __restrict__ weight) {
    int ks   = blockIdx.x;           // 0..63
    int nt   = threadIdx.x >> 5;     // 0..7
    int lane = threadIdx.x & 31;
    int n  = nt * 8 + (lane >> 2);
    int k0 = ks * 16 + (lane & 3) * 2;
    float wn = weight[n];
    float d0 = (float)(k0 + 1)  - wn;
    float d1 = (float)(k0 + 2)  - wn;
    float d2 = (float)(k0 + 9)  - wn;
    float d3 = (float)(k0 + 10) - wn;
    uint2 b;
    b.x = f2_h2(expf(-d0 * d0 * 0.01f), expf(-d1 * d1 * 0.01f));
    b.y = f2_h2(expf(-d2 * d2 * 0.01f), expf(-d3 * d3 * 0.01f));
    g_Bfrag[ks * 256 + nt * 32 + lane] = b;
}

static __device__ __forceinline__ void mma16816(float c[4],
        uint32_t a0, uint32_t a1, uint32_t a2, uint32_t a3,
        uint32_t b0, uint32_t b1) {
    asm volatile(
        "mma.sync.aligned.m16n8k16.row.col.f32.f16.f16.f32 "
        "{%0,%1,%2,%3}, {%4,%5,%6,%7}, {%8,%9}, {%0,%1,%2,%3};"
        : "+f"(c[0]), "+f"(c[1]), "+f"(c[2]), "+f"(c[3])
        : "r"(a0), "r"(a1), "r"(a2), "r"(a3), "r"(b0), "r"(b1));
}

__global__ void __launch_bounds__(THREADS)
gemm_hmma(const float* __restrict__ x, float* __restrict__ out, int rows)
{
    const int tid  = threadIdx.x;
    const int warp = tid >> 5;
    const int lane = tid & 31;
    const int r0   = blockIdx.x * MTILE + warp * 32;   // this warp's first row
    const int rq   = lane >> 2;                        // row within 8-group
    const int kc   = (lane & 3) * 2;                   // k-pair column

    const float* xw = x + (size_t)r0 * L_DENSE;

    float c[2][8][4];
    #pragma unroll
    for (int mt = 0; mt < 2; ++mt)
        #pragma unroll
        for (int nt = 0; nt < 8; ++nt)
            #pragma unroll
            for (int q = 0; q < 4; ++q) c[mt][nt][q] = 0.f;

    uint32_t a[2][4];
    uint2    b[8];

    auto loadA = [&](int ks, uint32_t dst[2][4]) {
        #pragma unroll
        for (int mt = 0; mt < 2; ++mt) {
            const float* p = xw + (size_t)(mt * 16 + rq) * L_DENSE + ks * 16 + kc;
            float2 v0 = *(const float2*)(p);
            float2 v1 = *(const float2*)(p + 8 * L_DENSE);
            float2 v2 = *(const float2*)(p + 8);
            float2 v3 = *(const float2*)(p + 8 * L_DENSE + 8);
            dst[mt][0] = f2_h2(v0.x, v0.y);
            dst[mt][1] = f2_h2(v1.x, v1.y);
            dst[mt][2] = f2_h2(v2.x, v2.y);
            dst[mt][3] = f2_h2(v3.x, v3.y);
        }
    };
    auto loadB = [&](int ks, uint2 dst[8]) {
        const uint2* bp = g_Bfrag + ks * 256 + lane;
        #pragma unroll
        for (int nt = 0; nt < 8; ++nt) dst[nt] = bp[nt * 32];
    };

    loadA(0, a);
    loadB(0, b);

    #pragma unroll 2
    for (int ks = 0; ks < NSTEPS; ++ks) {
        uint32_t an[2][4];
        uint2    bn[8];
        if (ks + 1 < NSTEPS) { loadA(ks + 1, an); loadB(ks + 1, bn); }

        #pragma unroll
        for (int mt = 0; mt < 2; ++mt)
            #pragma unroll
            for (int nt = 0; nt < 8; ++nt)
                mma16816(c[mt][nt], a[mt][0], a[mt][1], a[mt][2], a[mt][3],
                         b[nt].x, b[nt].y);

        if (ks + 1 < NSTEPS) {
            #pragma unroll
            for (int mt = 0; mt < 2; ++mt)
                #pragma unroll
                for (int q = 0; q < 4; ++q) a[mt][q] = an[mt][q];
            #pragma unroll
            for (int nt = 0; nt < 8; ++nt) b[nt] = bn[nt];
        }
    }

    // ---- epilogue: c[mt][nt] fragment (r,2c),(r,2c+1),(r+8,2c),(r+8,2c+1) ----
    #pragma unroll
    for (int mt = 0; mt < 2; ++mt) {
        int r = r0 + mt * 16 + rq;
        #pragma unroll
        for (int nt = 0; nt < 8; ++nt) {
            if (r < rows) {
                float2 v; v.x = c[mt][nt][0]; v.y = c[mt][nt][1];
                *(float2*)(out + (size_t)r * LT + nt * 8 + kc) = v;
            }
            if (r + 8 < rows) {
                float2 w; w.x = c[mt][nt][2]; w.y = c[mt][nt][3];
                *(float2*)(out + (size_t)(r + 8) * LT + nt * 8 + kc) = w;
            }
        }
    }
}

extern "C" void kernel_launch(void* const* d_in, const int* in_sizes, int n_in,
                              void* d_out, int out_size) {
    const float* x      = (const float*)d_in[0];
    const float* weight = (const float*)d_in[1];
    float* out          = (float*)d_out;

    const int rows = in_sizes[0] / L_DENSE;   // 131072

    precompute_frag<<<NSTEPS, 256>>>(weight);
    gemm_hmma<<<(rows + MTILE - 1) / MTILE, THREADS>>>(x, out, rows);
}

// round 11
// speedup vs baseline: 1.3703x; 1.0661x over previous
#include <cuda_runtime.h>
#include <cuda_fp16.h>
#include <cstdint>
#include <math.h>

#define L_DENSE 1024
#define LT      64
#define NSTEPS  64        // K / 16
#define MTILE   128       // rows per CTA (4 warps x 32)
#define THREADS 128

// W fragments, PERMUTED k-layout (lane c holds k = 4c..4c+3 within each k16 step),
// n-tiles paired into uint4 for LDG.128:
// g_Bfrag4[ks*128 + np*32 + lane] = { h2(W[na][k0],W[na][k0+1]), h2(W[na][k0+2],W[na][k0+3]),
//                                     h2(W[nb][k0],W[nb][k0+1]), h2(W[nb][k0+2],W[nb][k0+3]) }
// na = 16np + lane/4, nb = na + 8, k0 = ks*16 + (lane%4)*4
__device__ uint4 g_Bfrag4[NSTEPS * 4 * 32];

static __device__ __forceinline__ uint32_t f2_h2(float lo, float hi) {
    uint32_t u;
    asm("cvt.rn.f16x2.f32 %0, %1, %2;" : "=r"(u) : "f"(hi), "f"(lo));
    return u;
}

__global__ void precompute_frag(const float* __restrict__ weight) {
    int ks   = blockIdx.x;           // 0..63
    int np   = threadIdx.x >> 5;     // 0..3
    int lane = threadIdx.x & 31;
    int na = np * 16 + (lane >> 2);
    int nb = na + 8;
    int k0 = ks * 16 + (lane & 3) * 4;
    float wa = weight[na], wb = weight[nb];
    uint4 v;
    {
        float d0 = (float)(k0 + 1) - wa, d1 = (float)(k0 + 2) - wa;
        float d2 = (float)(k0 + 3) - wa, d3 = (float)(k0 + 4) - wa;
        v.x = f2_h2(expf(-d0 * d0 * 0.01f), expf(-d1 * d1 * 0.01f));
        v.y = f2_h2(expf(-d2 * d2 * 0.01f), expf(-d3 * d3 * 0.01f));
    }
    {
        float d0 = (float)(k0 + 1) - wb, d1 = (float)(k0 + 2) - wb;
        float d2 = (float)(k0 + 3) - wb, d3 = (float)(k0 + 4) - wb;
        v.z = f2_h2(expf(-d0 * d0 * 0.01f), expf(-d1 * d1 * 0.01f));
        v.w = f2_h2(expf(-d2 * d2 * 0.01f), expf(-d3 * d3 * 0.01f));
    }
    g_Bfrag4[ks * 128 + np * 32 + lane] = v;
}

static __device__ __forceinline__ void mma16816(float c[4],
        uint32_t a0, uint32_t a1, uint32_t a2, uint32_t a3,
        uint32_t b0, uint32_t b1) {
    asm volatile(
        "mma.sync.aligned.m16n8k16.row.col.f32.f16.f16.f32 "
        "{%0,%1,%2,%3}, {%4,%5,%6,%7}, {%8,%9}, {%0,%1,%2,%3};"
        : "+f"(c[0]), "+f"(c[1]), "+f"(c[2]), "+f"(c[3])
        : "r"(a0), "r"(a1), "r"(a2), "r"(a3), "r"(b0), "r"(b1));
}

__global__ void __launch_bounds__(THREADS)
gemm_hmma(const float* __restrict__ x, float* __restrict__ out, int rows)
{
    const int tid  = threadIdx.x;
    const int warp = tid >> 5;
    const int lane = tid & 31;
    const int r0   = blockIdx.x * MTILE + warp * 32;   // this warp's first row
    const int rq   = lane >> 2;                        // row within 8-group
    const int kq   = (lane & 3) * 4;                   // permuted k quad base
    const int cc   = (lane & 3) * 2;                   // C column pair (layout fixed)

    const float* xw = x + (size_t)r0 * L_DENSE;

    float c[2][8][4];
    #pragma unroll
    for (int mt = 0; mt < 2; ++mt)
        #pragma unroll
        for (int nt = 0; nt < 8; ++nt)
            #pragma unroll
            for (int q = 0; q < 4; ++q) c[mt][nt][q] = 0.f;

    uint32_t a[2][4];
    uint2    b[8];

    // A: one LDG.128 per (mt, row-half); permuted slots: a0/a2 = k quad of row rq,
    // a1/a3 = k quad of row rq+8 (low pair / high pair).
    auto loadA = [&](int ks, uint32_t dst[2][4]) {
        #pragma unroll
        for (int mt = 0; mt < 2; ++mt) {
            const float4* p = (const float4*)(xw + (size_t)(mt * 16 + rq) * L_DENSE + ks * 16 + kq);
            float4 v0 = __ldcs(p);
            float4 v1 = __ldcs(p + 2 * L_DENSE);   // +8 rows (8*1024 floats = 2048 float4)
            dst[mt][0] = f2_h2(v0.x, v0.y);
            dst[mt][2] = f2_h2(v0.z, v0.w);
            dst[mt][1] = f2_h2(v1.x, v1.y);
            dst[mt][3] = f2_h2(v1.z, v1.w);
        }
    };
    auto loadB = [&](int ks, uint2 dst[8]) {
        const uint4* bp = g_Bfrag4 + ks * 128 + lane;
        #pragma unroll
        for (int np = 0; np < 4; ++np) {
            uint4 v = bp[np * 32];
            dst[2 * np + 0].x = v.x;  dst[2 * np + 0].y = v.y;
            dst[2 * np + 1].x = v.z;  dst[2 * np + 1].y = v.w;
        }
    };

    loadA(0, a);
    loadB(0, b);

    #pragma unroll 2
    for (int ks = 0; ks < NSTEPS; ++ks) {
        uint32_t an[2][4];
        uint2    bn[8];
        if (ks + 1 < NSTEPS) { loadA(ks + 1, an); loadB(ks + 1, bn); }

        #pragma unroll
        for (int mt = 0; mt < 2; ++mt)
            #pragma unroll
            for (int nt = 0; nt < 8; ++nt)
                mma16816(c[mt][nt], a[mt][0], a[mt][1], a[mt][2], a[mt][3],
                         b[nt].x, b[nt].y);

        if (ks + 1 < NSTEPS) {
            #pragma unroll
            for (int mt = 0; mt < 2; ++mt)
                #pragma unroll
                for (int q = 0; q < 4; ++q) a[mt][q] = an[mt][q];
            #pragma unroll
            for (int nt = 0; nt < 8; ++nt) b[nt] = bn[nt];
        }
    }

    // ---- epilogue: C layout unchanged: (rq, 2c..2c+1) and (rq+8, ...) ----
    #pragma unroll
    for (int mt = 0; mt < 2; ++mt) {
        int r = r0 + mt * 16 + rq;
        #pragma unroll
        for (int nt = 0; nt < 8; ++nt) {
            if (r < rows) {
                float2 v; v.x = c[mt][nt][0]; v.y = c[mt][nt][1];
                __stcs((float2*)(out + (size_t)r * LT + nt * 8 + cc), v);
            }
            if (r + 8 < rows) {
                float2 w; w.x = c[mt][nt][2]; w.y = c[mt][nt][3];
                __stcs((float2*)(out + (size_t)(r + 8) * LT + nt * 8 + cc), w);
            }
        }
    }
}

extern "C" void kernel_launch(void* const* d_in, const int* in_sizes, int n_in,
                              void* d_out, int out_size) {
    const float* x      = (const float*)d_in[0];
    const float* weight = (const float*)d_in[1];
    float* out          = (float*)d_out;

    const int rows = in_sizes[0] / L_DENSE;   // 131072

    precompute_frag<<<NSTEPS, 128>>>(weight);
    gemm_hmma<<<(rows + MTILE - 1) / MTILE, THREADS>>>(x, out, rows);
}